// round 1
// baseline (speedup 1.0000x reference)
#include <cuda_runtime.h>
#include <cuda_bf16.h>

// Problem constants
#define B_   32
#define C_   192
#define H_   64
#define W_   64
#define OH_  32
#define OW_  32
#define NW_  6      // 192 bits -> 6 u32 words per pixel
#define NPIX_ (B_*H_*W_)

// Conv kernel tiling
#define OCB  64     // out-channels per block
#define TY   8      // output rows per block

// -------- device scratch (no mallocs allowed) --------
__device__ float g_mean[C_];
__device__ float g_rstd[C_];
__device__ float g_scale[2][C_];
__device__ float g_shift[2][C_];
__device__ unsigned g_wbits[2][C_][54];     // [br][oc][tap*6+w]
__device__ int      g_corr[2][C_][3];       // cx, cy, c00
__device__ unsigned g_abits[2][B_][H_][W_][NW_];   // ~6.3 MB
__device__ float    g_sc[B_][C_][OH_][OW_];        // ~25 MB (shared shortcut)

// ================= K1: per-channel mean / rstd =================
__global__ void k_stats(const float* __restrict__ x) {
    int c = blockIdx.x;
    int tid = threadIdx.x;
    float s = 0.f, ss = 0.f;
    for (int b = 0; b < B_; b++) {
        const float* p = x + ((size_t)(b * C_ + c)) * (H_ * W_);
        for (int i = tid; i < H_ * W_; i += 256) {
            float v = p[i];
            s += v;
            ss = fmaf(v, v, ss);
        }
    }
    __shared__ float sh1[256], sh2[256];
    sh1[tid] = s; sh2[tid] = ss;
    __syncthreads();
    for (int st = 128; st > 0; st >>= 1) {
        if (tid < st) { sh1[tid] += sh1[tid + st]; sh2[tid] += sh2[tid + st]; }
        __syncthreads();
    }
    if (tid == 0) {
        const float invn = 1.f / (float)(B_ * H_ * W_);
        float mu = sh1[0] * invn;
        float var = sh2[0] * invn - mu * mu;
        g_mean[c] = mu;
        g_rstd[c] = 1.0f / sqrtf(var + 1e-5f);
    }
}

// ================= K1b: per-branch affine threshold =================
__global__ void k_scaleshift(const float* __restrict__ g1, const float* __restrict__ b1,
                             const float* __restrict__ g2, const float* __restrict__ b2) {
    int i = blockIdx.x * blockDim.x + threadIdx.x;
    if (i >= 2 * C_) return;
    int br = i / C_, c = i % C_;
    float gamma = br ? g2[c] : g1[c];
    float beta  = br ? b2[c] : b1[c];
    float sc = gamma * g_rstd[c];
    g_scale[br][c] = sc;
    g_shift[br][c] = beta - sc * g_mean[c];
}

// ================= K2: pack weights + border corrections =================
__global__ void k_wpack(const float* __restrict__ w1, const float* __restrict__ w2) {
    int i = blockIdx.x * blockDim.x + threadIdx.x;
    if (i >= 2 * C_) return;
    int br = i / C_, oc = i % C_;
    const float* w = br ? w2 : w1;
    int cx = 0, cy = 0, c00 = 0;
    for (int ky = 0; ky < 3; ky++) {
        for (int kx = 0; kx < 3; kx++) {
            int t = ky * 3 + kx;
            int pop = 0;
            for (int wd = 0; wd < NW_; wd++) {
                unsigned bits = 0;
                for (int j = 0; j < 32; j++) {
                    int ic = wd * 32 + j;
                    float v = w[((oc * C_ + ic) * 3 + ky) * 3 + kx];
                    bits |= (v > 0.f) ? (1u << j) : 0u;
                }
                g_wbits[br][oc][t * NW_ + wd] = bits;
                pop += __popc(bits);
            }
            int contrib = C_ - 2 * pop;   // what a zero-padded tap would falsely add
            if (kx == 0) cx += contrib;
            if (ky == 0) cy += contrib;
            if (kx == 0 && ky == 0) c00 = contrib;
        }
    }
    g_corr[br][oc][0] = cx;
    g_corr[br][oc][1] = cy;
    g_corr[br][oc][2] = c00;
}

// ========== K3: fused binarize+pack (both branches) + avgpool shortcut ==========
// warp = one (b, oy); lane = ox. Each thread owns a 2x2 input pixel block.
__global__ void k_pack(const float* __restrict__ x) {
    __shared__ float s_scale[2 * C_], s_shift[2 * C_];
    int tid = threadIdx.x;
    for (int i = tid; i < 2 * C_; i += 256) {
        s_scale[i] = ((const float*)g_scale)[i];
        s_shift[i] = ((const float*)g_shift)[i];
    }
    __syncthreads();

    int gw = blockIdx.x * 8 + (tid >> 5);  // 0..1023
    int lane = tid & 31;                   // = ox
    int b = gw >> 5, oy = gw & 31;

    const float* px = x + ((size_t)b * C_) * (H_ * W_) + (2 * oy) * W_ + 2 * lane;
    float* psc = &g_sc[b][0][oy][lane];

    int y0 = 2 * oy, x0 = 2 * lane;

#pragma unroll
    for (int wd = 0; wd < NW_; wd++) {
        unsigned acc0 = 0, acc1 = 0, acc2 = 0, acc3 = 0;  // branch 0, pixels 00 01 10 11
        unsigned acd0 = 0, acd1 = 0, acd2 = 0, acd3 = 0;  // branch 1
#pragma unroll 8
        for (int j = 0; j < 32; j++) {
            int c = wd * 32 + j;
            const float* pc = px + (size_t)c * (H_ * W_);
            float2 r0 = *(const float2*)pc;
            float2 r1 = *(const float2*)(pc + W_);
            psc[(size_t)c * (OH_ * OW_)] = (r0.x + r0.y + r1.x + r1.y) * 0.25f;
            float s0 = s_scale[c],       t0 = s_shift[c];
            float s1 = s_scale[C_ + c],  t1 = s_shift[C_ + c];
            unsigned bit = 1u << j;
            if (fmaf(s0, r0.x, t0) > 0.f) acc0 |= bit;
            if (fmaf(s0, r0.y, t0) > 0.f) acc1 |= bit;
            if (fmaf(s0, r1.x, t0) > 0.f) acc2 |= bit;
            if (fmaf(s0, r1.y, t0) > 0.f) acc3 |= bit;
            if (fmaf(s1, r0.x, t1) > 0.f) acd0 |= bit;
            if (fmaf(s1, r0.y, t1) > 0.f) acd1 |= bit;
            if (fmaf(s1, r1.x, t1) > 0.f) acd2 |= bit;
            if (fmaf(s1, r1.y, t1) > 0.f) acd3 |= bit;
        }
        g_abits[0][b][y0][x0][wd]         = acc0;
        g_abits[0][b][y0][x0 + 1][wd]     = acc1;
        g_abits[0][b][y0 + 1][x0][wd]     = acc2;
        g_abits[0][b][y0 + 1][x0 + 1][wd] = acc3;
        g_abits[1][b][y0][x0][wd]         = acd0;
        g_abits[1][b][y0][x0 + 1][wd]     = acd1;
        g_abits[1][b][y0 + 1][x0][wd]     = acd2;
        g_abits[1][b][y0 + 1][x0 + 1][wd] = acd3;
    }
}

// ================= K4: XNOR-popcount conv + relu + shortcut =================
// grid: (4 y-groups, 3 oc-groups, 64 = br*32+b), block 256 = 32 ox x 8 ty
__global__ void __launch_bounds__(256) k_conv(const float* __restrict__ bias1,
                                              const float* __restrict__ bias2,
                                              float* __restrict__ out) {
    __shared__ __align__(16) unsigned s_act[17 * 65 * NW_];  // zero-padded tile
    __shared__ __align__(16) unsigned s_w[OCB * 64];
    __shared__ int s_corr[OCB][3];

    int tid = threadIdx.x;
    int ox = tid & 31, ty = tid >> 5;
    int ybase = blockIdx.x * TY;
    int ocbase = blockIdx.y * OCB;
    int zb = blockIdx.z;
    int br = zb >> 5, b = zb & 31;

    const unsigned* gab = &g_abits[br][b][0][0][0];
    for (int i = tid; i < 17 * 65 * NW_; i += 256) {
        int r = i / (65 * NW_);
        int rem = i % (65 * NW_);
        int xc = rem / NW_;
        int wd = rem % NW_;
        int yy = 2 * ybase - 1 + r;
        int xx = xc - 1;
        unsigned v = 0;
        if (yy >= 0 && xx >= 0) v = gab[(yy * W_ + xx) * NW_ + wd];
        s_act[i] = v;
    }
    const unsigned* gw = &g_wbits[br][ocbase][0];
    for (int i = tid; i < OCB * 54; i += 256) {
        int o = i / 54, t = i % 54;
        s_w[o * 64 + t] = gw[i];
    }
    for (int i = tid; i < OCB * 3; i += 256) {
        ((int*)s_corr)[i] = ((const int*)&g_corr[br][ocbase][0])[i];
    }
    __syncthreads();

    // activation patch -> registers (9 taps x 6 words)
    unsigned a[54];
#pragma unroll
    for (int ky = 0; ky < 3; ky++)
#pragma unroll
        for (int kx = 0; kx < 3; kx++)
#pragma unroll
            for (int wd = 0; wd < NW_; wd++)
                a[(ky * 3 + kx) * NW_ + wd] =
                    s_act[((2 * ty + ky) * 65 + (2 * ox + kx)) * NW_ + wd];

    int oy = ybase + ty;
    bool bx = (ox == 0), by = (oy == 0);
    const float* bias = br ? bias2 : bias1;

    float* po = out + (((size_t)b * (2 * C_) + br * C_ + ocbase) * OH_ + oy) * OW_ + ox;
    const float* psc = &g_sc[b][ocbase][oy][ox];

    for (int o = 0; o < OCB; o++) {
        const unsigned* wp = &s_w[o * 64];
        int mism = 0;
#pragma unroll
        for (int t = 0; t < 54; t++) mism += __popc(a[t] ^ wp[t]);
        int dot = 9 * C_ - 2 * mism;
        if (bx) dot -= s_corr[o][0];
        if (by) dot -= s_corr[o][1];
        if (bx && by) dot += s_corr[o][2];
        float y = (float)dot + __ldg(&bias[ocbase + o]);
        float v = fmaxf(y, 0.f) + psc[(size_t)o * (OH_ * OW_)];
        po[(size_t)o * (OH_ * OW_)] = v;
    }
}

// ================= launch =================
extern "C" void kernel_launch(void* const* d_in, const int* in_sizes, int n_in,
                              void* d_out, int out_size) {
    const float* x     = (const float*)d_in[0];
    const float* g1    = (const float*)d_in[1];
    const float* b1    = (const float*)d_in[2];
    const float* w1    = (const float*)d_in[3];
    const float* bias1 = (const float*)d_in[4];
    const float* g2    = (const float*)d_in[5];
    const float* b2    = (const float*)d_in[6];
    const float* w2    = (const float*)d_in[7];
    const float* bias2 = (const float*)d_in[8];
    float* out = (float*)d_out;

    k_stats<<<C_, 256>>>(x);
    k_scaleshift<<<2, C_>>>(g1, b1, g2, b2);
    k_wpack<<<2, C_>>>(w1, w2);
    k_pack<<<(B_ * OH_) / 8 * 8 / 8, 256>>>(x);   // 1024 warps -> 128 blocks
    dim3 gconv(OH_ / TY, C_ / OCB, 2 * B_);
    k_conv<<<gconv, 256>>>(bias1, bias2, out);
}

// round 2
// speedup vs baseline: 1.1315x; 1.1315x over previous
#include <cuda_runtime.h>
#include <cuda_bf16.h>

// Problem constants
#define B_   32
#define C_   192
#define H_   64
#define W_   64
#define OH_  32
#define OW_  32
#define NW_  6      // 192 bits -> 6 u32 words per pixel

// Conv kernel tiling
#define OCB  64     // out-channels per block
#define TY   8      // output rows per block

// -------- device scratch (no mallocs allowed) --------
__device__ float g_psum[8][C_];
__device__ float g_pss[8][C_];
__device__ float g_scale[2][C_];
__device__ float g_shift[2][C_];
__device__ unsigned g_wbits[2][C_][54];     // [br][oc][tap*6+w]
__device__ int      g_corr[2][C_][3];       // cx, cy, c00
__device__ unsigned g_abits[2][B_][H_][W_][NW_];   // ~6.3 MB
__device__ float    g_sc[B_][C_][OH_][OW_];        // ~25 MB (shared shortcut)

// ================= K1: per-channel partial sums (split-K over batch) =========
__global__ void k_stats(const float* __restrict__ x) {
    int c = blockIdx.x;
    int s = blockIdx.y;           // batch slice 0..7 (4 batches each)
    int tid = threadIdx.x;
    float sm = 0.f, ss = 0.f;
    for (int b = 4 * s; b < 4 * s + 4; b++) {
        const float4* p = (const float4*)(x + ((size_t)(b * C_ + c)) * (H_ * W_));
#pragma unroll
        for (int i = tid; i < (H_ * W_) / 4; i += 256) {
            float4 v = p[i];
            sm += (v.x + v.y) + (v.z + v.w);
            ss += fmaf(v.x, v.x, v.y * v.y) + fmaf(v.z, v.z, v.w * v.w);
        }
    }
    __shared__ float sh1[256], sh2[256];
    sh1[tid] = sm; sh2[tid] = ss;
    __syncthreads();
    for (int st = 128; st > 0; st >>= 1) {
        if (tid < st) { sh1[tid] += sh1[tid + st]; sh2[tid] += sh2[tid + st]; }
        __syncthreads();
    }
    if (tid == 0) {
        g_psum[s][c] = sh1[0];
        g_pss[s][c]  = sh2[0];
    }
}

// ================= K1b: finalize stats + per-branch affine threshold =========
__global__ void k_scaleshift(const float* __restrict__ g1, const float* __restrict__ b1,
                             const float* __restrict__ g2, const float* __restrict__ b2) {
    int i = blockIdx.x * blockDim.x + threadIdx.x;
    if (i >= 2 * C_) return;
    int br = i / C_, c = i % C_;
    float s = 0.f, q = 0.f;
#pragma unroll
    for (int k = 0; k < 8; k++) { s += g_psum[k][c]; q += g_pss[k][c]; }
    const float invn = 1.f / (float)(B_ * H_ * W_);
    float mu = s * invn;
    float var = q * invn - mu * mu;
    float rstd = rsqrtf(var + 1e-5f);
    float gamma = br ? g2[c] : g1[c];
    float beta  = br ? b2[c] : b1[c];
    float sc = gamma * rstd;
    g_scale[br][c] = sc;
    g_shift[br][c] = beta - sc * mu;
}

// ================= K2: pack weights + border corrections =================
__global__ void k_wpack(const float* __restrict__ w1, const float* __restrict__ w2) {
    int i = blockIdx.x * blockDim.x + threadIdx.x;
    if (i >= 2 * C_) return;
    int br = i / C_, oc = i % C_;
    const float* w = br ? w2 : w1;
    int cx = 0, cy = 0, c00 = 0;
    for (int ky = 0; ky < 3; ky++) {
        for (int kx = 0; kx < 3; kx++) {
            int t = ky * 3 + kx;
            int pop = 0;
            for (int wd = 0; wd < NW_; wd++) {
                unsigned bits = 0;
                for (int j = 0; j < 32; j++) {
                    int ic = wd * 32 + j;
                    float v = w[((oc * C_ + ic) * 3 + ky) * 3 + kx];
                    bits |= (v > 0.f) ? (1u << j) : 0u;
                }
                g_wbits[br][oc][t * NW_ + wd] = bits;
                pop += __popc(bits);
            }
            int contrib = C_ - 2 * pop;   // what a zero-padded tap would falsely add
            if (kx == 0) cx += contrib;
            if (ky == 0) cy += contrib;
            if (kx == 0 && ky == 0) c00 = contrib;
        }
    }
    g_corr[br][oc][0] = cx;
    g_corr[br][oc][1] = cy;
    g_corr[br][oc][2] = c00;
}

// ========== K3: fused binarize+pack (both branches) + avgpool shortcut ==========
// 3 warps per (b, oy), each warp owns 64 channels (2 bit-words). lane = ox.
// Each thread owns a 2x2 input pixel block.
__global__ void __launch_bounds__(256) k_pack(const float* __restrict__ x) {
    __shared__ float s_scale[2 * C_], s_shift[2 * C_];
    int tid = threadIdx.x;
    for (int i = tid; i < 2 * C_; i += 256) {
        s_scale[i] = ((const float*)g_scale)[i];
        s_shift[i] = ((const float*)g_shift)[i];
    }
    __syncthreads();

    int gw = blockIdx.x * 8 + (tid >> 5);  // 0..3071
    int lane = tid & 31;                   // = ox
    int b = gw / (OH_ * 3);
    int rem = gw % (OH_ * 3);
    int oy = rem / 3;
    int wp = rem % 3;                      // channel third: channels [64*wp, 64*wp+64)
    int c0 = wp * 64;

    const float* px = x + ((size_t)(b * C_ + c0)) * (H_ * W_) + (2 * oy) * W_ + 2 * lane;
    float* psc = &g_sc[b][c0][oy][lane];

    int y0 = 2 * oy, x0 = 2 * lane;

    // acc[wdl][br*4 + pixel]  (pixel: 00,01,10,11)
    unsigned acc[2][8];
#pragma unroll
    for (int wdl = 0; wdl < 2; wdl++)
#pragma unroll
        for (int k = 0; k < 8; k++) acc[wdl][k] = 0;

#pragma unroll
    for (int wdl = 0; wdl < 2; wdl++) {
#pragma unroll 8
        for (int j = 0; j < 32; j++) {
            int cl = wdl * 32 + j;           // local channel 0..63
            int c = c0 + cl;                 // global channel
            const float* pc = px + (size_t)cl * (H_ * W_);
            float2 r0 = *(const float2*)pc;
            float2 r1 = *(const float2*)(pc + W_);
            psc[(size_t)cl * (OH_ * OW_)] = (r0.x + r0.y + r1.x + r1.y) * 0.25f;
            float s0 = s_scale[c],       t0 = s_shift[c];
            float s1 = s_scale[C_ + c],  t1 = s_shift[C_ + c];
            unsigned bit = 1u << j;
            if (fmaf(s0, r0.x, t0) > 0.f) acc[wdl][0] |= bit;
            if (fmaf(s0, r0.y, t0) > 0.f) acc[wdl][1] |= bit;
            if (fmaf(s0, r1.x, t0) > 0.f) acc[wdl][2] |= bit;
            if (fmaf(s0, r1.y, t0) > 0.f) acc[wdl][3] |= bit;
            if (fmaf(s1, r0.x, t1) > 0.f) acc[wdl][4] |= bit;
            if (fmaf(s1, r0.y, t1) > 0.f) acc[wdl][5] |= bit;
            if (fmaf(s1, r1.x, t1) > 0.f) acc[wdl][6] |= bit;
            if (fmaf(s1, r1.y, t1) > 0.f) acc[wdl][7] |= bit;
        }
    }

    // write both bit-words of this channel group as one uint2 per pixel per branch
    int wd0 = 2 * wp;
#pragma unroll
    for (int br = 0; br < 2; br++) {
#pragma unroll
        for (int p = 0; p < 4; p++) {
            int yy = y0 + (p >> 1);
            int xx = x0 + (p & 1);
            uint2 v = make_uint2(acc[0][br * 4 + p], acc[1][br * 4 + p]);
            *(uint2*)&g_abits[br][b][yy][xx][wd0] = v;
        }
    }
}

// ================= K4: XNOR-popcount conv + relu + shortcut =================
// grid: (4 y-groups, 3 oc-groups, 64 = br*32+b), block 256 = 32 ox x 8 ty
__global__ void __launch_bounds__(256) k_conv(const float* __restrict__ bias1,
                                              const float* __restrict__ bias2,
                                              float* __restrict__ out) {
    __shared__ __align__(16) unsigned s_act[17 * 65 * NW_];   // 26520 B, zero-padded tile
    __shared__ __align__(16) uint4 s_w4[OCB * 14];            // 56 words per oc (2 zero pad)
    __shared__ int   s_corr[OCB * 3];
    __shared__ float s_bias[OCB];

    int tid = threadIdx.x;
    int ox = tid & 31, ty = tid >> 5;
    int ybase = blockIdx.x * TY;
    int ocbase = blockIdx.y * OCB;
    int zb = blockIdx.z;
    int br = zb >> 5, b = zb & 31;

    const unsigned* gab = &g_abits[br][b][0][0][0];
    for (int i = tid; i < 17 * 65 * NW_; i += 256) {
        int r = i / (65 * NW_);
        int rem = i % (65 * NW_);
        int xc = rem / NW_;
        int wd = rem % NW_;
        int yy = 2 * ybase - 1 + r;
        int xx = xc - 1;
        unsigned v = 0;
        if (yy >= 0 && xx >= 0) v = gab[(yy * W_ + xx) * NW_ + wd];
        s_act[i] = v;
    }
    const unsigned* gw = &g_wbits[br][ocbase][0];
    for (int i = tid; i < OCB * 56; i += 256) {
        int o = i / 56, t = i % 56;
        ((unsigned*)s_w4)[i] = (t < 54) ? gw[o * 54 + t] : 0u;
    }
    for (int i = tid; i < OCB * 3; i += 256)
        s_corr[i] = ((const int*)&g_corr[br][ocbase][0])[i];
    const float* bias = br ? bias2 : bias1;
    if (tid < OCB) s_bias[tid] = bias[ocbase + tid];
    __syncthreads();

    // activation patch -> registers (9 taps x 6 words, padded to 56)
    unsigned a[56];
#pragma unroll
    for (int ky = 0; ky < 3; ky++)
#pragma unroll
        for (int kx = 0; kx < 3; kx++)
#pragma unroll
            for (int wd = 0; wd < NW_; wd++)
                a[(ky * 3 + kx) * NW_ + wd] =
                    s_act[((2 * ty + ky) * 65 + (2 * ox + kx)) * NW_ + wd];
    a[54] = 0u; a[55] = 0u;

    int oy = ybase + ty;
    bool bx = (ox == 0), by = (oy == 0);

    float* po = out + (((size_t)b * (2 * C_) + br * C_ + ocbase) * OH_ + oy) * OW_ + ox;
    const float* psc = &g_sc[b][ocbase][oy][ox];

#pragma unroll 2
    for (int o = 0; o < OCB; o++) {
        const uint4* wp4 = &s_w4[o * 14];
        int m0 = 0, m1 = 0, m2 = 0, m3 = 0;
#pragma unroll
        for (int t = 0; t < 14; t++) {
            uint4 w = wp4[t];
            m0 += __popc(a[4 * t + 0] ^ w.x);
            m1 += __popc(a[4 * t + 1] ^ w.y);
            m2 += __popc(a[4 * t + 2] ^ w.z);
            m3 += __popc(a[4 * t + 3] ^ w.w);
        }
        int mism = (m0 + m1) + (m2 + m3);
        int dot = 9 * C_ - 2 * mism;
        if (bx) dot -= s_corr[o * 3 + 0];
        if (by) dot -= s_corr[o * 3 + 1];
        if (bx && by) dot += s_corr[o * 3 + 2];
        float y = (float)dot + s_bias[o];
        float v = fmaxf(y, 0.f) + psc[(size_t)o * (OH_ * OW_)];
        po[(size_t)o * (OH_ * OW_)] = v;
    }
}

// ================= launch =================
extern "C" void kernel_launch(void* const* d_in, const int* in_sizes, int n_in,
                              void* d_out, int out_size) {
    const float* x     = (const float*)d_in[0];
    const float* g1    = (const float*)d_in[1];
    const float* b1    = (const float*)d_in[2];
    const float* w1    = (const float*)d_in[3];
    const float* bias1 = (const float*)d_in[4];
    const float* g2    = (const float*)d_in[5];
    const float* b2    = (const float*)d_in[6];
    const float* w2    = (const float*)d_in[7];
    const float* bias2 = (const float*)d_in[8];
    float* out = (float*)d_out;

    k_stats<<<dim3(C_, 8), 256>>>(x);
    k_scaleshift<<<2, C_>>>(g1, b1, g2, b2);
    k_wpack<<<2, C_>>>(w1, w2);
    k_pack<<<(B_ * OH_ * 3) / 8, 256>>>(x);     // 3072 warps -> 384 blocks
    dim3 gconv(OH_ / TY, C_ / OCB, 2 * B_);
    k_conv<<<gconv, 256>>>(bias1, bias2, out);
}

// round 4
// speedup vs baseline: 1.7929x; 1.5846x over previous
#include <cuda_runtime.h>
#include <cstdint>

// Problem constants
#define B_   32
#define C_   192
#define H_   64
#define W_   64
#define OH_  32
#define OW_  32
#define NW_  6      // 192 bits -> 6 u32 words per pixel

// -------- device scratch (no mallocs allowed) --------
__device__ float g_psum[8][C_];
__device__ float g_pss[8][C_];
__device__ float g_scale[2][C_];
__device__ float g_shift[2][C_];
__device__ unsigned g_wbf[2 * 9 * C_ * (C_ / 2)];        // bf16x2 weights [br][tap][oc][ic/2]
__device__ unsigned g_abits[2][B_][H_][W_][NW_];         // packed sign bits per pixel
__device__ float    g_sc[B_][C_][OH_][OW_];              // shared avgpool shortcut

// ---------------- PTX helpers (all sm_80-compatible) ----------------
__device__ __forceinline__ uint32_t smem_to_u32(const void* p) {
    uint32_t a;
    asm("{ .reg .u64 t; cvta.to.shared.u64 t, %1; cvt.u32.u64 %0, t; }" : "=r"(a) : "l"(p));
    return a;
}
#define STS128(r0, r1, r2, r3, addr) \
    asm volatile("st.shared.v4.b32 [%0], {%1, %2, %3, %4};" \
        :: "r"(addr), "r"(r0), "r"(r1), "r"(r2), "r"(r3) : "memory")
#define LDSM_X4(r, addr) \
    asm volatile("ldmatrix.sync.aligned.m8n8.x4.shared.b16 {%0,%1,%2,%3}, [%4];" \
        : "=r"((r)[0]), "=r"((r)[1]), "=r"((r)[2]), "=r"((r)[3]) : "r"(addr))
#define MMA16816(d, a, b0, b1) \
    asm volatile("mma.sync.aligned.m16n8k16.row.col.f32.bf16.bf16.f32 " \
        "{%0,%1,%2,%3}, {%4,%5,%6,%7}, {%8,%9}, {%0,%1,%2,%3};" \
        : "+f"((d)[0]), "+f"((d)[1]), "+f"((d)[2]), "+f"((d)[3]) \
        : "r"((a)[0]), "r"((a)[1]), "r"((a)[2]), "r"((a)[3]), "r"(b0), "r"(b1))

// ================= K1: per-channel partial sums =================
__global__ void k_stats(const float* __restrict__ x) {
    int c = blockIdx.x;
    int s = blockIdx.y;
    int tid = threadIdx.x;
    float sm = 0.f, ss = 0.f;
    for (int b = 4 * s; b < 4 * s + 4; b++) {
        const float4* p = (const float4*)(x + ((size_t)(b * C_ + c)) * (H_ * W_));
#pragma unroll
        for (int i = tid; i < (H_ * W_) / 4; i += 256) {
            float4 v = p[i];
            sm += (v.x + v.y) + (v.z + v.w);
            ss += fmaf(v.x, v.x, v.y * v.y) + fmaf(v.z, v.z, v.w * v.w);
        }
    }
    __shared__ float sh1[256], sh2[256];
    sh1[tid] = sm; sh2[tid] = ss;
    __syncthreads();
    for (int st = 128; st > 0; st >>= 1) {
        if (tid < st) { sh1[tid] += sh1[tid + st]; sh2[tid] += sh2[tid + st]; }
        __syncthreads();
    }
    if (tid == 0) { g_psum[s][c] = sh1[0]; g_pss[s][c] = sh2[0]; }
}

// ================= K1b: finalize stats + thresholds =================
__global__ void k_scaleshift(const float* __restrict__ g1, const float* __restrict__ b1,
                             const float* __restrict__ g2, const float* __restrict__ b2) {
    int i = blockIdx.x * blockDim.x + threadIdx.x;
    if (i >= 2 * C_) return;
    int br = i / C_, c = i % C_;
    float s = 0.f, q = 0.f;
#pragma unroll
    for (int k = 0; k < 8; k++) { s += g_psum[k][c]; q += g_pss[k][c]; }
    const float invn = 1.f / (float)(B_ * H_ * W_);
    float mu = s * invn;
    float var = q * invn - mu * mu;
    float rstd = rsqrtf(var + 1e-5f);
    float gamma = br ? g2[c] : g1[c];
    float beta  = br ? b2[c] : b1[c];
    float sc = gamma * rstd;
    g_scale[br][c] = sc;
    g_shift[br][c] = beta - sc * mu;
}

// ================= K2: pack weights to bf16 +-1, [br][tap][oc][ic] =========
__global__ void k_wpack(const float* __restrict__ w1, const float* __restrict__ w2) {
    int i = blockIdx.x * 256 + threadIdx.x;
    if (i >= 2 * 9 * C_ * (C_ / 2)) return;
    int cw = i % (C_ / 2);
    int t = i / (C_ / 2);
    int oc = t % C_; t /= C_;
    int tap = t % 9;
    int br = t / 9;
    int ky = tap / 3, kx = tap % 3;
    const float* w = br ? w2 : w1;
    int c0 = 2 * cw;
    float v0 = w[((oc * C_ + c0) * 3 + ky) * 3 + kx];
    float v1 = w[((oc * C_ + c0 + 1) * 3 + ky) * 3 + kx];
    unsigned lo = v0 > 0.f ? 0x3F80u : 0xBF80u;
    unsigned hi = v1 > 0.f ? 0x3F80u : 0xBF80u;
    g_wbf[i] = lo | (hi << 16);
}

// ========== K3: fused binarize+pack (both branches) + avgpool shortcut ==========
__global__ void __launch_bounds__(256) k_pack(const float* __restrict__ x) {
    __shared__ float s_scale[2 * C_], s_shift[2 * C_];
    int tid = threadIdx.x;
    for (int i = tid; i < 2 * C_; i += 256) {
        s_scale[i] = ((const float*)g_scale)[i];
        s_shift[i] = ((const float*)g_shift)[i];
    }
    __syncthreads();

    int gw = blockIdx.x * 8 + (tid >> 5);
    int lane = tid & 31;
    int b = gw / (OH_ * 3);
    int rem = gw % (OH_ * 3);
    int oy = rem / 3;
    int wp = rem % 3;
    int c0 = wp * 64;

    const float* px = x + ((size_t)(b * C_ + c0)) * (H_ * W_) + (2 * oy) * W_ + 2 * lane;
    float* psc = &g_sc[b][c0][oy][lane];
    int y0 = 2 * oy, x0 = 2 * lane;

    unsigned acc[2][8];
#pragma unroll
    for (int wdl = 0; wdl < 2; wdl++)
#pragma unroll
        for (int k = 0; k < 8; k++) acc[wdl][k] = 0;

#pragma unroll
    for (int wdl = 0; wdl < 2; wdl++) {
#pragma unroll 8
        for (int j = 0; j < 32; j++) {
            int cl = wdl * 32 + j;
            int c = c0 + cl;
            const float* pc = px + (size_t)cl * (H_ * W_);
            float2 r0 = *(const float2*)pc;
            float2 r1 = *(const float2*)(pc + W_);
            psc[(size_t)cl * (OH_ * OW_)] = (r0.x + r0.y + r1.x + r1.y) * 0.25f;
            float s0 = s_scale[c],      t0 = s_shift[c];
            float s1 = s_scale[C_ + c], t1 = s_shift[C_ + c];
            unsigned bit = 1u << j;
            if (fmaf(s0, r0.x, t0) > 0.f) acc[wdl][0] |= bit;
            if (fmaf(s0, r0.y, t0) > 0.f) acc[wdl][1] |= bit;
            if (fmaf(s0, r1.x, t0) > 0.f) acc[wdl][2] |= bit;
            if (fmaf(s0, r1.y, t0) > 0.f) acc[wdl][3] |= bit;
            if (fmaf(s1, r0.x, t1) > 0.f) acc[wdl][4] |= bit;
            if (fmaf(s1, r0.y, t1) > 0.f) acc[wdl][5] |= bit;
            if (fmaf(s1, r1.x, t1) > 0.f) acc[wdl][6] |= bit;
            if (fmaf(s1, r1.y, t1) > 0.f) acc[wdl][7] |= bit;
        }
    }

    int wd0 = 2 * wp;
#pragma unroll
    for (int br = 0; br < 2; br++)
#pragma unroll
        for (int p = 0; p < 4; p++) {
            int yy = y0 + (p >> 1);
            int xx = x0 + (p & 1);
            uint2 v = make_uint2(acc[0][br * 4 + p], acc[1][br * 4 + p]);
            *(uint2*)&g_abits[br][b][yy][xx][wd0] = v;
        }
}

// ================= K4: HMMA bf16 implicit-GEMM conv =================
// CTA: M=128 output pixels (4 rows x 32 ox), N=192 oc, K=9 taps x 192 ic.
// 512 threads = 16 warps in a 4(M) x 4(N) grid; warp tile 32x48.
// smem: A[128][200] bf16 (51200 B) + B[192][200] bf16 (76800 B) = 128000 B,
// reused as float S[192][132] (101376 B) for the epilogue transpose.
#define CONV_SMEM 128000
#define A_STRIDE 400   // bytes per A row (200 bf16)
#define B_STRIDE 400

__global__ void __launch_bounds__(512, 1) k_conv(const float* __restrict__ bias1,
                                                 const float* __restrict__ bias2,
                                                 float* __restrict__ out) {
    extern __shared__ __align__(16) char smem[];
    __shared__ float s_bias[C_];
    uint32_t sb = smem_to_u32(smem);
    const uint32_t A_OFF = 0, B_OFF = 51200;

    int tid = threadIdx.x;
    int lane = tid & 31, w = tid >> 5;
    int wm = w & 3, wn = w >> 2;
    int yg = blockIdx.x, br = blockIdx.y, b = blockIdx.z;
    int oy0 = yg * 4;

    const float* bias = br ? bias2 : bias1;
    if (tid < C_) s_bias[tid] = bias[tid];

    const unsigned* gab = &g_abits[br][b][0][0][0];
    const uint4* gw = (const uint4*)g_wbf + (size_t)br * 9 * C_ * 24;

    // accumulators: warp tile 32(M) x 48(N) -> 2 m-tiles x 6 n-tiles x 4 fp32
    float d[2][6][4];
#pragma unroll
    for (int mt = 0; mt < 2; mt++)
#pragma unroll
        for (int nt = 0; nt < 6; nt++)
#pragma unroll
            for (int e = 0; e < 4; e++) d[mt][nt][e] = 0.f;

    // ldmatrix base addresses (k-chunk advances by 32 bytes)
    uint32_t a_addr[2];
#pragma unroll
    for (int mt = 0; mt < 2; mt++) {
        int row = wm * 32 + mt * 16 + (lane & 15);
        int col8 = (lane >> 4) * 8;
        a_addr[mt] = sb + A_OFF + row * A_STRIDE + col8 * 2;
    }
    uint32_t b_addr[3];
    {
        int sub = lane & 7, g2 = lane >> 3;
#pragma unroll
        for (int np = 0; np < 3; np++) {
            int row = wn * 48 + np * 16 + sub + ((g2 >> 1) << 3);
            int kcol = (g2 & 1) * 8;
            b_addr[np] = sb + B_OFF + row * B_STRIDE + kcol * 2;
        }
    }

    // expand indices (tap-invariant parts)
    int ep = tid & 127;           // pixel within CTA for i = tid
    int er = ep >> 5, eox = ep & 31;

    for (int tap = 0; tap < 9; tap++) {
        int ky = tap / 3, kx = tap - 3 * (tap / 3);

        // ---- expand A tile: packed bits -> bf16 {+1,-1} with 0 padding ----
#pragma unroll
        for (int i = tid; i < 768; i += 512) {
            int p = i & 127, wd = i >> 7;
            int r = p >> 5, ox = p & 31;
            int y = 2 * (oy0 + r) + ky - 1;
            int xx = 2 * ox + kx - 1;
            bool ok = (y >= 0) && (xx >= 0);
            unsigned bits = ok ? gab[(y * W_ + xx) * NW_ + wd] : 0u;
            unsigned nb = ok ? ~bits : 0u;
            unsigned fill = ok ? 0x3F803F80u : 0u;
            uint32_t base = sb + A_OFF + p * A_STRIDE + wd * 64;
#pragma unroll
            for (int q = 0; q < 4; q++) {
                int j = 8 * q;
                unsigned v0 = fill | (((nb >> j) & 1u) << 15)       | (((nb >> (j + 1)) & 1u) << 31);
                unsigned v1 = fill | (((nb >> (j + 2)) & 1u) << 15) | (((nb >> (j + 3)) & 1u) << 31);
                unsigned v2 = fill | (((nb >> (j + 4)) & 1u) << 15) | (((nb >> (j + 5)) & 1u) << 31);
                unsigned v3 = fill | (((nb >> (j + 6)) & 1u) << 15) | (((nb >> (j + 7)) & 1u) << 31);
                STS128(v0, v1, v2, v3, base + q * 16);
            }
        }
        (void)er; (void)eox;

        // ---- stream B tile: 192 oc x 192 ic bf16 for this tap ----
        const uint4* gwt = gw + tap * C_ * 24;
#pragma unroll
        for (int it = 0; it < 9; it++) {
            int i = tid + it * 512;            // 0..4607
            uint4 wv = gwt[i];
            int oc = i / 24, q = i % 24;
            STS128(wv.x, wv.y, wv.z, wv.w, sb + B_OFF + oc * B_STRIDE + q * 16);
        }
        __syncthreads();

        // ---- MMA: 12 k-chunks of 16 ----
#pragma unroll
        for (int kc = 0; kc < 12; kc++) {
            uint32_t af[2][4];
#pragma unroll
            for (int mt = 0; mt < 2; mt++) LDSM_X4(af[mt], a_addr[mt] + kc * 32);
            uint32_t bf[3][4];
#pragma unroll
            for (int np = 0; np < 3; np++) LDSM_X4(bf[np], b_addr[np] + kc * 32);
#pragma unroll
            for (int mt = 0; mt < 2; mt++)
#pragma unroll
                for (int nt = 0; nt < 6; nt++) {
                    int np = nt >> 1, o = (nt & 1) * 2;
                    MMA16816(d[mt][nt], af[mt], bf[np][o], bf[np][o + 1]);
                }
        }
        __syncthreads();   // protect smem before next tap overwrites
    }

    // ---- epilogue: transpose via smem, fuse bias+relu+shortcut, coalesced out ----
    float* S = (float*)smem;     // S[c][m], stride 132 floats
#pragma unroll
    for (int mt = 0; mt < 2; mt++)
#pragma unroll
        for (int nt = 0; nt < 6; nt++)
#pragma unroll
            for (int e = 0; e < 4; e++) {
                int m = wm * 32 + mt * 16 + (lane >> 2) + ((e >> 1) << 3);
                int c = wn * 48 + nt * 8 + ((lane & 3) << 1) + (e & 1);
                S[c * 132 + m] = d[mt][nt][e];
            }
    __syncthreads();

    size_t ob = ((size_t)b * (2 * C_) + (size_t)br * C_) * (OH_ * OW_) + (size_t)yg * 128;
    const float* scp = &g_sc[b][0][0][0] + yg * 128;
#pragma unroll
    for (int i = tid; i < 24576; i += 512) {
        int c = i >> 7, m = i & 127;
        float v = S[c * 132 + m] + s_bias[c];
        v = fmaxf(v, 0.f) + scp[(size_t)c * (OH_ * OW_) + m];
        out[ob + (size_t)c * (OH_ * OW_) + m] = v;
    }
}

// ================= launch =================
extern "C" void kernel_launch(void* const* d_in, const int* in_sizes, int n_in,
                              void* d_out, int out_size) {
    const float* x     = (const float*)d_in[0];
    const float* g1    = (const float*)d_in[1];
    const float* b1    = (const float*)d_in[2];
    const float* w1    = (const float*)d_in[3];
    const float* bias1 = (const float*)d_in[4];
    const float* g2    = (const float*)d_in[5];
    const float* b2    = (const float*)d_in[6];
    const float* w2    = (const float*)d_in[7];
    const float* bias2 = (const float*)d_in[8];
    float* out = (float*)d_out;

    cudaFuncSetAttribute(k_conv, cudaFuncAttributeMaxDynamicSharedMemorySize, CONV_SMEM);

    k_stats<<<dim3(C_, 8), 256>>>(x);
    k_scaleshift<<<2, C_>>>(g1, b1, g2, b2);
    k_wpack<<<(2 * 9 * C_ * (C_ / 2) + 255) / 256, 256>>>(w1, w2);
    k_pack<<<(B_ * OH_ * 3) / 8, 256>>>(x);
    dim3 gconv(OH_ / 4, 2, B_);
    k_conv<<<gconv, 512, CONV_SMEM>>>(bias1, bias2, out);
}